// round 11
// baseline (speedup 1.0000x reference)
#include <cuda_runtime.h>
#include <cuda_fp16.h>
#include <cstdint>

// ---------------------------------------------------------------------------
// MLPLinkPredictor: score[e] = W2 . relu(W1 [h[src];h[dst]] + b1) + b2
//
// W1 [h_s; h_d] = W1a h_s + W1b h_d. Precompute C[n,0:512] = h @ Wt^T (+b1 on
// first half) on tensor cores (fp16 in / fp32 accum / fp16 out; C is 51 MB,
// L2-resident). cp.async 4-stage pipeline, one barrier per k-chunk.
// Edge phase: register double-buffered gather (8 LDG.128 in flight),
// half2 relu-dot, W2 in registers, butterfly transpose-reduce.
// ---------------------------------------------------------------------------

#define N_NODES 50000
#define N_FEAT  256
#define N_OUT   512
#define N_NODES_PAD 50048
#define FULL 0xffffffffu

// Scratch (device globals: allocation-free per harness rules)
__device__ __half g_Ch[(size_t)N_NODES_PAD * N_OUT];   // 51.2 MB
__device__ __half g_Af[(size_t)N_NODES_PAD * N_FEAT];  // 25.6 MB fp16 h (padded rows zero)
__device__ __half g_Bf[(size_t)N_OUT * N_FEAT];        // 256 KB fp16 repacked W1

// ---------------------------------------------------------------------------
// h (fp32) -> g_Af (fp16), zero padding rows. 8 elements per thread.
// ---------------------------------------------------------------------------
__global__ void split_h_kernel(const float* __restrict__ h) {
    size_t i8 = ((size_t)blockIdx.x * blockDim.x + threadIdx.x) * 8;
    if (i8 >= (size_t)N_NODES_PAD * N_FEAT) return;
    size_t row = i8 / N_FEAT;

    __half hv[8];
    if (row < N_NODES) {
        float4 f0 = *reinterpret_cast<const float4*>(&h[i8]);
        float4 f1 = *reinterpret_cast<const float4*>(&h[i8 + 4]);
        float x[8] = {f0.x, f0.y, f0.z, f0.w, f1.x, f1.y, f1.z, f1.w};
#pragma unroll
        for (int i = 0; i < 8; i++) hv[i] = __float2half_rn(x[i]);
    } else {
#pragma unroll
        for (int i = 0; i < 8; i++) hv[i] = __ushort_as_half((unsigned short)0);
    }
    *reinterpret_cast<uint4*>(&g_Af[i8]) = *reinterpret_cast<uint4*>(hv);
}

// ---------------------------------------------------------------------------
// Repack W1_w [256,512] into Wt [512,256] fp16.
//   Wt[j,k] = (j < 256) ? W1[j,k] : W1[j-256, 256+k]
// ---------------------------------------------------------------------------
__global__ void split_w_kernel(const float* __restrict__ W1) {
    size_t i4 = (size_t)blockIdx.x * blockDim.x + threadIdx.x;
    size_t total4 = (size_t)N_OUT * N_FEAT / 4;
    if (i4 >= total4) return;
    size_t base = i4 * 4;
    int j = (int)(base / N_FEAT);
    int k = (int)(base % N_FEAT);

    const float* srcp = (j < N_FEAT) ? &W1[(size_t)j * (2 * N_FEAT) + k]
                                     : &W1[(size_t)(j - N_FEAT) * (2 * N_FEAT) + N_FEAT + k];
    float4 v = *reinterpret_cast<const float4*>(srcp);

    __half hv[4];
    float x[4] = {v.x, v.y, v.z, v.w};
#pragma unroll
    for (int i = 0; i < 4; i++) hv[i] = __float2half_rn(x[i]);
    *reinterpret_cast<uint2*>(&g_Bf[base]) = *reinterpret_cast<uint2*>(hv);
}

// ---------------------------------------------------------------------------
// GEMM: C[50048,512] = A @ B^T via mma.m16n8k16 fp16, fp32 accum.
// cp.async 4-stage pipeline, ONE barrier per k-chunk. Block 128x128, BK=32,
// 8 warps (2M x 4N), warp tile 64x32. fp16 out, b1 folded into cols [0,256).
// ---------------------------------------------------------------------------
#define SK 40                      // 32 + 8 pad halves per smem row
#define TILE_H (128 * SK)          // halves per tile
#define BUF_H  (2 * TILE_H)        // A, B per stage

#define MMA_F16(c, a, b)                                                           \
    asm volatile("mma.sync.aligned.m16n8k16.row.col.f32.f16.f16.f32 "              \
                 "{%0,%1,%2,%3}, {%4,%5,%6,%7}, {%8,%9}, {%0,%1,%2,%3};"           \
                 : "+f"((c)[0]), "+f"((c)[1]), "+f"((c)[2]), "+f"((c)[3])          \
                 : "r"((a)[0]), "r"((a)[1]), "r"((a)[2]), "r"((a)[3]),             \
                   "r"((b)[0]), "r"((b)[1]))

#define LDSM_X4(r, p)                                                              \
    do {                                                                           \
        uint32_t _ad = (uint32_t)__cvta_generic_to_shared(p);                      \
        asm volatile("ldmatrix.sync.aligned.m8n8.x4.shared.b16 {%0,%1,%2,%3}, [%4];" \
                     : "=r"((r)[0]), "=r"((r)[1]), "=r"((r)[2]), "=r"((r)[3])      \
                     : "r"(_ad));                                                  \
    } while (0)

#define CP_ASYNC16(saddr, gptr)                                                    \
    asm volatile("{\n\t.reg .u64 g;\n\tcvta.to.global.u64 g, %1;\n\t"              \
                 "cp.async.cg.shared.global [%0], [g], 16;\n\t}"                   \
                 :: "r"(saddr), "l"(gptr))
#define CP_COMMIT() asm volatile("cp.async.commit_group;")
#define CP_WAIT2()  asm volatile("cp.async.wait_group 2;")
#define CP_WAIT1()  asm volatile("cp.async.wait_group 1;")
#define CP_WAIT0()  asm volatile("cp.async.wait_group 0;")

extern __shared__ __half sm_dyn[];

__device__ __forceinline__ void stage_chunk(uint32_t smem_base, int buf,
                                            int bm, int bn, int k0, int tid) {
    uint32_t b = smem_base + (uint32_t)buf * (BUF_H * 2);
#pragma unroll
    for (int rep = 0; rep < 2; rep++) {
        int chunk = tid + rep * 256;           // 0..511
        int row   = chunk >> 2;                // 0..127
        int c8    = (chunk & 3) * 8;           // halves
        uint32_t off = (uint32_t)(row * SK + c8) * 2;
        CP_ASYNC16(b + off,
                   &g_Af[(size_t)(bm * 128 + row) * N_FEAT + k0 + c8]);
        CP_ASYNC16(b + TILE_H * 2 + off,
                   &g_Bf[(size_t)(bn * 128 + row) * N_FEAT + k0 + c8]);
    }
}

__global__ __launch_bounds__(256, 2)
void gemm_f16_kernel(const float* __restrict__ b1) {
    const int tid  = threadIdx.x;
    const int wid  = tid >> 5;
    const int lane = tid & 31;
    const int bn   = blockIdx.x;          // 0..3
    const int bm   = blockIdx.y;          // 0..390
    const int wm   = (wid & 1) * 64;
    const int wn   = (wid >> 1) * 32;
    const int g    = lane >> 2;
    const int t    = lane & 3;
    const int lm   = lane >> 3;
    const int lr8  = lane & 7;

    float acc[4][4][4];
#pragma unroll
    for (int mt = 0; mt < 4; mt++)
#pragma unroll
        for (int nt = 0; nt < 4; nt++)
#pragma unroll
            for (int i = 0; i < 4; i++) acc[mt][nt][i] = 0.f;

    uint32_t smb = (uint32_t)__cvta_generic_to_shared(sm_dyn);

    stage_chunk(smb, 0, bm, bn, 0, tid);  CP_COMMIT();
    stage_chunk(smb, 1, bm, bn, 32, tid); CP_COMMIT();

#pragma unroll 1
    for (int it = 0; it < 8; it++) {
        // Stage chunk it+2 into buffer (it+2)&3 before this iteration's
        // barrier. Safe: that buffer held chunk it-2; every warp passed
        // barrier(it-1), which is after compute(it-2) completed for all.
        if (it + 2 < 8) {
            stage_chunk(smb, (it + 2) & 3, bm, bn, (it + 2) * 32, tid);
            CP_COMMIT();
        }
        // Groups committed so far: chunks 0..min(it+2,7). Need chunk it done.
        if (it < 6) CP_WAIT2(); else if (it == 6) CP_WAIT1(); else CP_WAIT0();
        __syncthreads();   // the ONLY barrier per iteration

        __half (*sA)[SK] = reinterpret_cast<__half(*)[SK]>(sm_dyn + (it & 3) * BUF_H);
        __half (*sB)[SK] = reinterpret_cast<__half(*)[SK]>(sm_dyn + (it & 3) * BUF_H + TILE_H);

#pragma unroll
        for (int kk = 0; kk < 32; kk += 16) {
            uint32_t a[4][4], bh[4][2];
#pragma unroll
            for (int mt = 0; mt < 4; mt++) {
                int r = wm + mt * 16 + (lm & 1) * 8 + lr8;
                int c = kk + (lm >> 1) * 8;
                LDSM_X4(a[mt], &sA[r][c]);
            }
            {
                int c  = kk + (lm & 1) * 8;
                int r0 = wn + (lm >> 1) * 8 + lr8;
                uint32_t rb[4];
                LDSM_X4(rb, &sB[r0][c]);
                bh[0][0] = rb[0]; bh[0][1] = rb[1]; bh[1][0] = rb[2]; bh[1][1] = rb[3];
                LDSM_X4(rb, &sB[r0 + 16][c]);
                bh[2][0] = rb[0]; bh[2][1] = rb[1]; bh[3][0] = rb[2]; bh[3][1] = rb[3];
            }
#pragma unroll
            for (int mt = 0; mt < 4; mt++)
#pragma unroll
                for (int nt = 0; nt < 4; nt++)
                    MMA_F16(acc[mt][nt], a[mt], bh[nt]);
        }
    }

    // All warps are past the last barrier and their own compute; no further
    // smem writes happen, so no trailing barrier needed before epilogue.
#pragma unroll
    for (int mt = 0; mt < 4; mt++) {
#pragma unroll
        for (int nt = 0; nt < 4; nt++) {
            int row0 = bm * 128 + wm + mt * 16 + g;
            int col  = bn * 128 + wn + nt * 8 + t * 2;
            float bias0 = 0.f, bias1 = 0.f;
            if (col < N_FEAT) { bias0 = b1[col]; bias1 = b1[col + 1]; }
            __half2 v01 = __floats2half2_rn(acc[mt][nt][0] + bias0, acc[mt][nt][1] + bias1);
            __half2 v23 = __floats2half2_rn(acc[mt][nt][2] + bias0, acc[mt][nt][3] + bias1);
            *reinterpret_cast<__half2*>(&g_Ch[(size_t)row0 * N_OUT + col])       = v01;
            *reinterpret_cast<__half2*>(&g_Ch[(size_t)(row0 + 8) * N_OUT + col]) = v23;
        }
    }
}

// ---------------------------------------------------------------------------
// Edge kernel: one warp per 16-edge batch; 4-edge chunks with register
// double-buffering -> 8 independent LDG.128 in flight while computing the
// previous chunk (L2 MLP ~2x round 9). Butterfly transpose-reduce at the end.
// ---------------------------------------------------------------------------
struct EdgeCtx {
    int sl, dl, lane;
    float wf[8];
};

__device__ __forceinline__ void edge_load4(const EdgeCtx& cx, int e0,
                                           uint4* A, uint4* B) {
#pragma unroll
    for (int i = 0; i < 4; i++) {
        int s = __shfl_sync(FULL, cx.sl, e0 + i);
        int d = __shfl_sync(FULL, cx.dl, e0 + i);
        A[i] = *reinterpret_cast<const uint4*>(&g_Ch[(size_t)s * N_OUT + cx.lane * 8]);
        B[i] = *reinterpret_cast<const uint4*>(&g_Ch[(size_t)d * N_OUT + N_FEAT + cx.lane * 8]);
    }
}

__device__ __forceinline__ void edge_comp4(const EdgeCtx& cx, int e0,
                                           const uint4* A, const uint4* B, float* v) {
    const __half2 zero2 = __float2half2_rn(0.f);
#pragma unroll
    for (int i = 0; i < 4; i++) {
        const __half2* ha = reinterpret_cast<const __half2*>(&A[i]);
        const __half2* hb = reinterpret_cast<const __half2*>(&B[i]);
        float acc = 0.f;
#pragma unroll
        for (int j = 0; j < 4; j++) {
            __half2 tmax = __hmax2(__hadd2(ha[j], hb[j]), zero2);
            float2 f = __half22float2(tmax);
            acc = fmaf(f.x, cx.wf[2 * j],     acc);
            acc = fmaf(f.y, cx.wf[2 * j + 1], acc);
        }
        v[e0 + i] = acc;
    }
}

__global__ __launch_bounds__(256)
void edge_kernel(const int* __restrict__ src, const int* __restrict__ dst,
                 const float* __restrict__ W2w, const float* __restrict__ W2b,
                 float* __restrict__ out, int E) {
    int gtid = blockIdx.x * blockDim.x + threadIdx.x;
    int lane = gtid & 31;
    int warp = gtid >> 5;
    int base = warp * 16;
    if (base >= E) return;

    EdgeCtx cx;
    cx.lane = lane;
    {
        float4 w0 = reinterpret_cast<const float4*>(W2w)[lane * 2];
        float4 w1 = reinterpret_cast<const float4*>(W2w)[lane * 2 + 1];
        cx.wf[0] = w0.x; cx.wf[1] = w0.y; cx.wf[2] = w0.z; cx.wf[3] = w0.w;
        cx.wf[4] = w1.x; cx.wf[5] = w1.y; cx.wf[6] = w1.z; cx.wf[7] = w1.w;
    }
    float b2 = W2b[0];

    int idx = base + (lane & 15);
    cx.sl = (idx < E) ? src[idx] : 0;
    cx.dl = (idx < E) ? dst[idx] : 0;

    float v[16];
    uint4 A0[4], B0[4], A1[4], B1[4];

    edge_load4(cx, 0, A0, B0);
    edge_load4(cx, 4, A1, B1);
    edge_comp4(cx, 0, A0, B0, v);
    edge_load4(cx, 8, A0, B0);
    edge_comp4(cx, 4, A1, B1, v);
    edge_load4(cx, 12, A1, B1);
    edge_comp4(cx, 8, A0, B0, v);
    edge_comp4(cx, 12, A1, B1, v);

    // 4-stage butterfly over bits 0..3, then fold the two 16-lane halves.
#pragma unroll
    for (int m = 8; m >= 1; m >>= 1) {
#pragma unroll
        for (int e = 0; e < m; e++) {
            float up   = (lane & m) ? v[e]     : v[e + m];
            float keep = (lane & m) ? v[e + m] : v[e];
            v[e] = keep + __shfl_xor_sync(FULL, up, m);
        }
    }
    v[0] += __shfl_xor_sync(FULL, v[0], 16);

    if (lane < 16 && base + lane < E) out[base + lane] = v[0] + b2;
}

// ---------------------------------------------------------------------------
extern "C" void kernel_launch(void* const* d_in, const int* in_sizes, int n_in,
                              void* d_out, int out_size) {
    const float* h    = (const float*)d_in[0];
    const int*   src  = (const int*)  d_in[1];
    const int*   dst  = (const int*)  d_in[2];
    const float* W1w  = (const float*)d_in[3];
    const float* W1b  = (const float*)d_in[4];
    const float* W2w  = (const float*)d_in[5];
    const float* W2b  = (const float*)d_in[6];
    float* out = (float*)d_out;

    const int E = in_sizes[1];   // 800000 edges

    // 1) fp16 conversions / weight repack
    size_t n8 = (size_t)N_NODES_PAD * N_FEAT / 8;
    split_h_kernel<<<(unsigned)((n8 + 255) / 256), 256>>>(h);
    size_t w4 = (size_t)N_OUT * N_FEAT / 4;
    split_w_kernel<<<(unsigned)((w4 + 255) / 256), 256>>>(W1w);

    // 2) Node projection GEMM (fp16, cp.async 4-stage, 1 barrier/chunk)
    static int smem_set = 0;
    const int smem_bytes = 4 * BUF_H * 2;   // 4 stages * (A,B) = 81920 bytes
    if (!smem_set) {
        cudaFuncSetAttribute(gemm_f16_kernel,
                             cudaFuncAttributeMaxDynamicSharedMemorySize, smem_bytes);
        smem_set = 1;
    }
    dim3 ggrid(N_OUT / 128, N_NODES_PAD / 128);
    gemm_f16_kernel<<<ggrid, 256, smem_bytes>>>(W1b);

    // 3) Per-edge gather + relu-dot: one warp per 16 edges
    int nwarps  = (E + 15) / 16;
    int eblocks = (nwarps + 7) / 8;
    edge_kernel<<<eblocks, 256>>>(src, dst, W2w, W2b, out, E);
}

// round 12
// speedup vs baseline: 1.4342x; 1.4342x over previous
#include <cuda_runtime.h>
#include <cuda_fp16.h>
#include <cstdint>

// ---------------------------------------------------------------------------
// MLPLinkPredictor: score[e] = W2 . relu(W1 [h[src];h[dst]] + b1) + b2
//
// W1 [h_s; h_d] = W1a h_s + W1b h_d. Precompute C[n,0:512] = h @ Wt^T (+b1 on
// first half) on tensor cores (fp16 in / fp32 accum / fp16 out; C 51 MB,
// L2-resident). GEMM is A-resident: each CTA converts its 64-row fp32 h tile
// to fp16 smem ONCE (full K), then loops over the 4 N-tiles streaming only B
// (L2-resident) through a 3-stage cp.async pipeline. No split_h kernel, no
// g_Af array, A read from DRAM exactly once.
// Edge phase: round-9 proven version (half2 gather + relu-dot, W2 in regs,
// 16-edge butterfly transpose-reduce).
// ---------------------------------------------------------------------------

#define N_NODES 50000
#define N_FEAT  256
#define N_OUT   512
#define N_NODES_PAD 50048
#define FULL 0xffffffffu

// Scratch (device globals: allocation-free per harness rules)
__device__ __half g_Ch[(size_t)N_NODES_PAD * N_OUT];   // 51.2 MB
__device__ __half g_Bf[(size_t)N_OUT * N_FEAT];        // 256 KB fp16 repacked W1

// ---------------------------------------------------------------------------
// Repack W1_w [256,512] into Wt [512,256] fp16.
//   Wt[j,k] = (j < 256) ? W1[j,k] : W1[j-256, 256+k]
// ---------------------------------------------------------------------------
__global__ void split_w_kernel(const float* __restrict__ W1) {
    size_t i4 = (size_t)blockIdx.x * blockDim.x + threadIdx.x;
    size_t total4 = (size_t)N_OUT * N_FEAT / 4;
    if (i4 >= total4) return;
    size_t base = i4 * 4;
    int j = (int)(base / N_FEAT);
    int k = (int)(base % N_FEAT);

    const float* srcp = (j < N_FEAT) ? &W1[(size_t)j * (2 * N_FEAT) + k]
                                     : &W1[(size_t)(j - N_FEAT) * (2 * N_FEAT) + N_FEAT + k];
    float4 v = *reinterpret_cast<const float4*>(srcp);

    __half hv[4];
    float x[4] = {v.x, v.y, v.z, v.w};
#pragma unroll
    for (int i = 0; i < 4; i++) hv[i] = __float2half_rn(x[i]);
    *reinterpret_cast<uint2*>(&g_Bf[base]) = *reinterpret_cast<uint2*>(hv);
}

// ---------------------------------------------------------------------------
// GEMM: C[50048,512] = fp16(h) @ B^T, A-resident full-K in smem.
// BM=64 (grid 782), BN=128 per bn step, BK=64 per pipeline chunk.
// 8 warps: 2 along M (wm 0/32) x 4 along N (wn 0/32/64/96); warp tile 32x32.
// 16 chunks total = 4 bn x 4 k; 3-stage cp.async pipeline for B.
// ---------------------------------------------------------------------------
#define BMM   64
#define SKA   264                      // 256 + 8 pad (halves); LDSM conflict-free
#define SKB   72                       // 64 + 8 pad (halves)
#define A_BYTES (BMM * SKA * 2)        // 33792
#define BTILE_BYTES (128 * SKB * 2)    // 18432
#define SMEM_TOTAL_B (A_BYTES + 3 * BTILE_BYTES)   // 89088

#define MMA_F16(c, a, b)                                                           \
    asm volatile("mma.sync.aligned.m16n8k16.row.col.f32.f16.f16.f32 "              \
                 "{%0,%1,%2,%3}, {%4,%5,%6,%7}, {%8,%9}, {%0,%1,%2,%3};"           \
                 : "+f"((c)[0]), "+f"((c)[1]), "+f"((c)[2]), "+f"((c)[3])          \
                 : "r"((a)[0]), "r"((a)[1]), "r"((a)[2]), "r"((a)[3]),             \
                   "r"((b)[0]), "r"((b)[1]))

#define LDSM_X4(r, p)                                                              \
    do {                                                                           \
        uint32_t _ad = (uint32_t)__cvta_generic_to_shared(p);                      \
        asm volatile("ldmatrix.sync.aligned.m8n8.x4.shared.b16 {%0,%1,%2,%3}, [%4];" \
                     : "=r"((r)[0]), "=r"((r)[1]), "=r"((r)[2]), "=r"((r)[3])      \
                     : "r"(_ad));                                                  \
    } while (0)

#define CP_ASYNC16(saddr, gptr)                                                    \
    asm volatile("{\n\t.reg .u64 g;\n\tcvta.to.global.u64 g, %1;\n\t"              \
                 "cp.async.cg.shared.global [%0], [g], 16;\n\t}"                   \
                 :: "r"(saddr), "l"(gptr))
#define CP_COMMIT() asm volatile("cp.async.commit_group;")
#define CP_WAIT1()  asm volatile("cp.async.wait_group 1;")
#define CP_WAIT0()  asm volatile("cp.async.wait_group 0;")

extern __shared__ __half sm_dyn[];

// Stage one B chunk: rows [bn*128, bn*128+128), k cols [k0, k0+64) -> buf.
__device__ __forceinline__ void stage_B(uint32_t smb, int buf, int chunk_lin, int tid) {
    int bn = chunk_lin >> 2;
    int k0 = (chunk_lin & 3) * 64;
    uint32_t b = smb + A_BYTES + (uint32_t)buf * BTILE_BYTES;
#pragma unroll
    for (int rep = 0; rep < 4; rep++) {
        int c   = tid + rep * 256;         // 0..1023
        int row = c >> 3;                  // 0..127
        int c8  = (c & 7) * 8;             // halves within 64
        uint32_t off = (uint32_t)(row * SKB + c8) * 2;
        CP_ASYNC16(b + off, &g_Bf[(size_t)(bn * 128 + row) * N_FEAT + k0 + c8]);
    }
}

__global__ __launch_bounds__(256, 2)
void gemm_f16_kernel(const float* __restrict__ h, const float* __restrict__ b1) {
    const int tid  = threadIdx.x;
    const int wid  = tid >> 5;
    const int lane = tid & 31;
    const int bm   = blockIdx.x;          // 0..781
    const int wm   = (wid & 1) * 32;
    const int wn   = (wid >> 1) * 32;
    const int g    = lane >> 2;
    const int t    = lane & 3;
    const int lm   = lane >> 3;
    const int lr8  = lane & 7;

    uint32_t smb = (uint32_t)__cvta_generic_to_shared(sm_dyn);
    __half (*sA)[SKA] = reinterpret_cast<__half(*)[SKA]>(sm_dyn);

    // Kick off B chunks 0,1 first so they overlap with the A conversion.
    stage_B(smb, 0, 0, tid); CP_COMMIT();
    stage_B(smb, 1, 1, tid); CP_COMMIT();

    // ---- A prologue: load 64x256 fp32 rows, convert to fp16, full-K smem ----
#pragma unroll
    for (int i = 0; i < 16; i++) {
        int idx = tid + i * 256;          // 0..4095 float4 slots
        int row = idx >> 6;               // 0..63
        int c4  = (idx & 63) * 4;         // fp32 col
        int grow = bm * BMM + row;
        float4 v = make_float4(0.f, 0.f, 0.f, 0.f);
        if (grow < N_NODES)
            v = *reinterpret_cast<const float4*>(&h[(size_t)grow * N_FEAT + c4]);
        __half hv[4];
        hv[0] = __float2half_rn(v.x); hv[1] = __float2half_rn(v.y);
        hv[2] = __float2half_rn(v.z); hv[3] = __float2half_rn(v.w);
        *reinterpret_cast<uint2*>(&sA[row][c4]) = *reinterpret_cast<uint2*>(hv);
    }

    float acc[2][4][4];
#pragma unroll
    for (int mt = 0; mt < 2; mt++)
#pragma unroll
        for (int nt = 0; nt < 4; nt++)
#pragma unroll
            for (int i = 0; i < 4; i++) acc[mt][nt][i] = 0.f;

#pragma unroll 1
    for (int c = 0; c < 16; c++) {
        if (c < 15) CP_WAIT1(); else CP_WAIT0();
        __syncthreads();    // B chunk c visible to all; also covers A STS (c==0)
                            // and guards buffer (c+2)%3 (all compute of chunk
                            // c-1 done before this barrier)

        if (c + 2 < 16) { stage_B(smb, (c + 2) % 3, c + 2, tid); CP_COMMIT(); }

        __half (*sB)[SKB] = reinterpret_cast<__half(*)[SKB]>(
            sm_dyn + (A_BYTES / 2) + (c % 3) * (BTILE_BYTES / 2));
        const int kbase = (c & 3) * 64;   // A global k offset for this chunk

#pragma unroll
        for (int kk = 0; kk < 64; kk += 16) {
            uint32_t a[2][4], bh[4][2];
#pragma unroll
            for (int mt = 0; mt < 2; mt++) {
                int r = wm + mt * 16 + (lm & 1) * 8 + lr8;
                int ca = kbase + kk + (lm >> 1) * 8;
                LDSM_X4(a[mt], &sA[r][ca]);
            }
            {
                int cb = kk + (lm & 1) * 8;
                int r0 = wn + (lm >> 1) * 8 + lr8;
                uint32_t rb[4];
                LDSM_X4(rb, &sB[r0][cb]);
                bh[0][0] = rb[0]; bh[0][1] = rb[1]; bh[1][0] = rb[2]; bh[1][1] = rb[3];
                LDSM_X4(rb, &sB[r0 + 16][cb]);
                bh[2][0] = rb[0]; bh[2][1] = rb[1]; bh[3][0] = rb[2]; bh[3][1] = rb[3];
            }
#pragma unroll
            for (int mt = 0; mt < 2; mt++)
#pragma unroll
                for (int nt = 0; nt < 4; nt++)
                    MMA_F16(acc[mt][nt], a[mt], bh[nt]);
        }

        // End of a bn group (4 k-chunks done): epilogue + reset accumulators.
        if ((c & 3) == 3) {
            int bn = c >> 2;
#pragma unroll
            for (int mt = 0; mt < 2; mt++) {
#pragma unroll
                for (int nt = 0; nt < 4; nt++) {
                    int row0 = bm * BMM + wm + mt * 16 + g;
                    int col  = bn * 128 + wn + nt * 8 + t * 2;
                    float bias0 = 0.f, bias1 = 0.f;
                    if (col < N_FEAT) { bias0 = b1[col]; bias1 = b1[col + 1]; }
                    __half2 v01 = __floats2half2_rn(acc[mt][nt][0] + bias0,
                                                    acc[mt][nt][1] + bias1);
                    __half2 v23 = __floats2half2_rn(acc[mt][nt][2] + bias0,
                                                    acc[mt][nt][3] + bias1);
                    *reinterpret_cast<__half2*>(&g_Ch[(size_t)row0 * N_OUT + col])       = v01;
                    *reinterpret_cast<__half2*>(&g_Ch[(size_t)(row0 + 8) * N_OUT + col]) = v23;
#pragma unroll
                    for (int i = 0; i < 4; i++) acc[mt][nt][i] = 0.f;
                }
            }
        }
    }
}

// ---------------------------------------------------------------------------
// Edge kernel (round-9 proven): one warp per 16-edge batch. W2 in 8 regs/lane,
// b1 folded in C, half2 add+relu, fp32 dot, 16-value butterfly
// transpose-reduce; lanes l and l+16 reduce halves, final xor-16 fold.
// ---------------------------------------------------------------------------
__global__ __launch_bounds__(256)
void edge_kernel(const int* __restrict__ src, const int* __restrict__ dst,
                 const float* __restrict__ W2w, const float* __restrict__ W2b,
                 float* __restrict__ out, int E) {
    int gtid = blockIdx.x * blockDim.x + threadIdx.x;
    int lane = gtid & 31;
    int warp = gtid >> 5;
    int base = warp * 16;
    if (base >= E) return;

    float4 w0 = reinterpret_cast<const float4*>(W2w)[lane * 2];
    float4 w1 = reinterpret_cast<const float4*>(W2w)[lane * 2 + 1];
    float wf[8] = {w0.x, w0.y, w0.z, w0.w, w1.x, w1.y, w1.z, w1.w};
    float b2 = W2b[0];

    int idx = base + (lane & 15);
    int sl = (idx < E) ? src[idx] : 0;
    int dl = (idx < E) ? dst[idx] : 0;

    const __half2 zero2 = __float2half2_rn(0.f);
    float v[16];

#pragma unroll
    for (int e = 0; e < 16; e++) {
        int s = __shfl_sync(FULL, sl, e);
        int d = __shfl_sync(FULL, dl, e);

        uint4 va = *reinterpret_cast<const uint4*>(&g_Ch[(size_t)s * N_OUT + lane * 8]);
        uint4 vb = *reinterpret_cast<const uint4*>(&g_Ch[(size_t)d * N_OUT + N_FEAT + lane * 8]);
        const __half2* ha = reinterpret_cast<const __half2*>(&va);
        const __half2* hb = reinterpret_cast<const __half2*>(&vb);

        float acc = 0.f;
#pragma unroll
        for (int j = 0; j < 4; j++) {
            __half2 tmax = __hmax2(__hadd2(ha[j], hb[j]), zero2);
            float2 f = __half22float2(tmax);
            acc = fmaf(f.x, wf[2 * j],     acc);
            acc = fmaf(f.y, wf[2 * j + 1], acc);
        }
        v[e] = acc;
    }

#pragma unroll
    for (int m = 8; m >= 1; m >>= 1) {
#pragma unroll
        for (int e = 0; e < m; e++) {
            float up   = (lane & m) ? v[e]     : v[e + m];
            float keep = (lane & m) ? v[e + m] : v[e];
            v[e] = keep + __shfl_xor_sync(FULL, up, m);
        }
    }
    v[0] += __shfl_xor_sync(FULL, v[0], 16);

    if (lane < 16 && base + lane < E) out[base + lane] = v[0] + b2;
}

// ---------------------------------------------------------------------------
extern "C" void kernel_launch(void* const* d_in, const int* in_sizes, int n_in,
                              void* d_out, int out_size) {
    const float* h    = (const float*)d_in[0];
    const int*   src  = (const int*)  d_in[1];
    const int*   dst  = (const int*)  d_in[2];
    const float* W1w  = (const float*)d_in[3];
    const float* W1b  = (const float*)d_in[4];
    const float* W2w  = (const float*)d_in[5];
    const float* W2b  = (const float*)d_in[6];
    float* out = (float*)d_out;

    const int E = in_sizes[1];   // 800000 edges

    // 1) Weight repack to fp16 (tiny)
    size_t w4 = (size_t)N_OUT * N_FEAT / 4;
    split_w_kernel<<<(unsigned)((w4 + 255) / 256), 256>>>(W1w);

    // 2) Node projection GEMM, A-resident full-K (h read from DRAM once)
    static int smem_set = 0;
    if (!smem_set) {
        cudaFuncSetAttribute(gemm_f16_kernel,
                             cudaFuncAttributeMaxDynamicSharedMemorySize, SMEM_TOTAL_B);
        smem_set = 1;
    }
    gemm_f16_kernel<<<N_NODES_PAD / BMM, 256, SMEM_TOTAL_B>>>(h, W1b);

    // 3) Per-edge gather + relu-dot: one warp per 16 edges
    int nwarps  = (E + 15) / 16;
    int eblocks = (nwarps + 7) / 8;
    edge_kernel<<<eblocks, 256>>>(src, dst, W2w, W2b, out, E);
}